// round 16
// baseline (speedup 1.0000x reference)
#include <cuda_runtime.h>
#include <cuda_fp16.h>
#include <cstdint>

// ---------------- problem constants ----------------
#define T_TOKENS 16384
#define DMODEL   2048
#define NEXP     64
#define MT       64
#define NCTAS    (T_TOKENS / MT)      // 256
#define NTHREADS 320                  // 8 consumer warps + 2 producer warps
#define BK       32
#define KT       (DMODEL / BK)        // 64
#define NSTAGE   4
#define SCALE    2048.0f
#define INVS     (1.0f / 2048.0f)

// ---------------- output layout (fp32, reference return order) ----------------
#define OFF_W    ((size_t)0)
#define OFF_I    ((size_t)32768)
#define OFF_P    ((size_t)65536)
#define OFF_ENT  ((size_t)1114112)
#define OFF_CONF ((size_t)1114113)
#define OFF_UTIL ((size_t)1114114)

// ---------------- smem ring: 4 stages x (AH,AM,BH,BM), rows 64B data @ 80B stride ----
#define RSTR     80
#define AH_OFF   0
#define AM_OFF   (64 * RSTR)            // 5120
#define BH_OFF   (2 * 64 * RSTR)        // 10240
#define BM_OFF   (3 * 64 * RSTR)        // 15360
#define STAGE_B  (4 * 64 * RSTR)        // 20480
#define DSM_BYTES (NSTAGE * STAGE_B)    // 81920
#define LSTR     66                      // logits row stride (floats)

// ---------------- device globals ----------------
__device__ __half g_Wh[NEXP * DMODEL];
__device__ __half g_Wm[NEXP * DMODEL];
__device__ float  g_ent;
__device__ float  g_conf;
__device__ int    g_counts[NEXP];
__device__ int    g_done;

// ---------------- helpers ----------------
__device__ __forceinline__ uint32_t smem_u32(const void* p) {
    uint32_t a;
    asm("{ .reg .u64 t; cvta.to.shared.u64 t, %1; cvt.u32.u64 %0, t; }" : "=r"(a) : "l"(p));
    return a;
}
#define STS128(addr, a, b, c, d) \
    asm volatile("st.shared.v4.b32 [%0], {%1,%2,%3,%4};" :: "r"(addr), "r"(a), "r"(b), "r"(c), "r"(d) : "memory")
#define CP_ASYNC16(dst, src) \
    asm volatile("cp.async.cg.shared.global [%0], [%1], 16;" :: "r"(dst), "l"(src) : "memory")
#define CP_COMMIT() asm volatile("cp.async.commit_group;" ::: "memory")
#define CP_WAIT0()  asm volatile("cp.async.wait_group 0;" ::: "memory")

#define MBAR_INIT(addr, cnt) \
    asm volatile("mbarrier.init.shared.b64 [%0], %1;" :: "r"(addr), "r"((uint32_t)(cnt)) : "memory")
#define MBAR_ARRIVE(addr) \
    asm volatile("mbarrier.arrive.shared.b64 _, [%0];" :: "r"(addr) : "memory")
#define MBAR_WAIT(addr, ph) do { \
    uint32_t _d; \
    do { \
        asm volatile("{\n\t.reg .pred p;\n\tmbarrier.try_wait.parity.shared.b64 p, [%1], %2;\n\tselp.b32 %0, 1, 0, p;\n\t}" \
            : "=r"(_d) : "r"(addr), "r"((uint32_t)(ph)) : "memory"); \
    } while (!_d); } while (0)

__device__ __forceinline__ void ldsm4(uint32_t& r0, uint32_t& r1, uint32_t& r2, uint32_t& r3, uint32_t a) {
    asm volatile("ldmatrix.sync.aligned.m8n8.x4.shared.b16 {%0,%1,%2,%3}, [%4];"
                 : "=r"(r0), "=r"(r1), "=r"(r2), "=r"(r3) : "r"(a));
}
__device__ __forceinline__ void mma16816(float* c, const uint32_t* a, const uint32_t* b) {
    asm volatile("mma.sync.aligned.m16n8k16.row.col.f32.f16.f16.f32 "
                 "{%0,%1,%2,%3},{%4,%5,%6,%7},{%8,%9},{%0,%1,%2,%3};"
                 : "+f"(c[0]), "+f"(c[1]), "+f"(c[2]), "+f"(c[3])
                 : "r"(a[0]), "r"(a[1]), "r"(a[2]), "r"(a[3]), "r"(b[0]), "r"(b[1]));
}

// two-limb fp16 split of a float pair -> packed H and scaled-M half2s
__device__ __forceinline__ void cvt2(float a, float b, uint32_t& H, uint32_t& M) {
    __half2 h = __floats2half2_rn(a, b);
    float2 hf = __half22float2(h);
    __half2 m = __floats2half2_rn((a - hf.x) * SCALE, (b - hf.y) * SCALE);
    H = *reinterpret_cast<uint32_t*>(&h);
    M = *reinterpret_cast<uint32_t*>(&m);
}

// strict ordering with lowest-index tie-break (matches jax top_k)
__device__ __forceinline__ bool ordgt(float a, int ia, float b, int ib) {
    return (a > b) || (a == b && ia < ib);
}

// ---------------- prep: zero stats + split W into fp16 limbs ----------------
__global__ void prep_kernel(const float* __restrict__ W) {
    if (blockIdx.x == 0) {
        if (threadIdx.x == 0) { g_ent = 0.0f; g_conf = 0.0f; g_done = 0; }
        if (threadIdx.x < NEXP) g_counts[threadIdx.x] = 0;
    }
    int i = (blockIdx.x * 256 + threadIdx.x) * 4;
    if (i < NEXP * DMODEL) {
        float4 f = *(const float4*)(W + i);
        uint32_t h0, m0, h1, m1;
        cvt2(f.x, f.y, h0, m0);
        cvt2(f.z, f.w, h1, m1);
        *(uint2*)(g_Wh + i) = make_uint2(h0, h1);
        *(uint2*)(g_Wm + i) = make_uint2(m0, m1);
    }
}

// producer: one tile — B cp.async, cvt staged x -> STS, refill LDG, publish
__device__ __forceinline__ void produce_tile(
    int tile, float4* buf, int stg, int ph,
    uint32_t full_b, uint32_t empty_b, uint32_t smbase,
    uint32_t aHb, uint32_t aMb, uint32_t bHb, uint32_t bMb,
    const float* xrow, const __half* bSH, const __half* bSM)
{
    const uint32_t full_s  = full_b  + stg * 8;
    const uint32_t empty_s = empty_b + stg * 8;
    const uint32_t so = (uint32_t)(stg * STAGE_B);

    MBAR_WAIT(empty_s, ph);

    // B limbs via cp.async (64B per limb per row-thread)
    const size_t ko = (size_t)tile * BK;
    #pragma unroll
    for (int j = 0; j < 4; j++) {
        CP_ASYNC16(bHb + so + j * 16, (const void*)(bSH + ko + j * 8));
        CP_ASYNC16(bMb + so + j * 16, (const void*)(bSM + ko + j * 8));
    }
    CP_COMMIT();

    // A: cvt staged 32 floats -> limb rows
    #pragma unroll
    for (int c = 0; c < 4; c++) {
        float4 f0 = buf[2 * c], f1 = buf[2 * c + 1];
        uint32_t H[4], M[4];
        cvt2(f0.x, f0.y, H[0], M[0]); cvt2(f0.z, f0.w, H[1], M[1]);
        cvt2(f1.x, f1.y, H[2], M[2]); cvt2(f1.z, f1.w, H[3], M[3]);
        STS128(aHb + so + c * 16, H[0], H[1], H[2], H[3]);
        STS128(aMb + so + c * 16, M[0], M[1], M[2], M[3]);
    }

    // refill this buffer with x(tile+2)
    if (tile + 2 < KT) {
        const float4* xn = (const float4*)(xrow + (size_t)(tile + 2) * BK);
        #pragma unroll
        for (int j = 0; j < 8; j++) buf[j] = xn[j];
    }

    CP_WAIT0();           // B landed
    MBAR_ARRIVE(full_s);  // publish stage
}

// ---------------- main fused router ----------------
__global__ __launch_bounds__(NTHREADS, 2)
void router_kernel(const float* __restrict__ x, float* __restrict__ out) {
    extern __shared__ __align__(16) char dsm[];
    __shared__ __align__(8) unsigned long long mbar[2 * NSTAGE];  // full[4], empty[4]
    __shared__ int hist[NEXP];
    __shared__ int s_last;

    const int t    = threadIdx.x;
    const int wid  = t >> 5;
    const int lane = t & 31;
    const int mbase = blockIdx.x * MT;
    const uint32_t smbase = smem_u32(dsm);
    const uint32_t full_b  = smem_u32(&mbar[0]);
    const uint32_t empty_b = smem_u32(&mbar[NSTAGE]);

    if (t == 0) {
        #pragma unroll
        for (int s = 0; s < NSTAGE; s++) {
            MBAR_INIT(full_b + s * 8, 64);    // 2 producer warps
            MBAR_INIT(empty_b + s * 8, 256);  // 8 consumer warps
        }
    }
    if (t < NEXP) hist[t] = 0;
    __syncthreads();

    if (wid >= 8) {
        // ================= PRODUCER (warps 8-9, 64 threads) =================
        const int pt = t - 256;                       // 0..63: token row & expert row
        const float* xrow = x + (size_t)(mbase + pt) * DMODEL;
        const __half* bSH = g_Wh + (size_t)pt * DMODEL;
        const __half* bSM = g_Wm + (size_t)pt * DMODEL;
        const uint32_t aHb = smbase + AH_OFF + (uint32_t)(pt * RSTR);
        const uint32_t aMb = smbase + AM_OFF + (uint32_t)(pt * RSTR);
        const uint32_t bHb = smbase + BH_OFF + (uint32_t)(pt * RSTR);
        const uint32_t bMb = smbase + BM_OFF + (uint32_t)(pt * RSTR);

        float4 bufA[8], bufB[8];
        {
            const float4* x0 = (const float4*)xrow;
            const float4* x1 = (const float4*)(xrow + BK);
            #pragma unroll
            for (int j = 0; j < 8; j++) { bufA[j] = x0[j]; bufB[j] = x1[j]; }
        }

        int stg = 0, ph = 1;   // producer starts phase 1: first empty-waits pass
        for (int tile = 0; tile < KT; tile += 2) {
            produce_tile(tile, bufA, stg, ph, full_b, empty_b, smbase,
                         aHb, aMb, bHb, bMb, xrow, bSH, bSM);
            stg++; if (stg == NSTAGE) { stg = 0; ph ^= 1; }
            produce_tile(tile + 1, bufB, stg, ph, full_b, empty_b, smbase,
                         aHb, aMb, bHb, bMb, xrow, bSH, bSM);
            stg++; if (stg == NSTAGE) { stg = 0; ph ^= 1; }
        }
    } else {
        // ================= CONSUMER (warps 0-7) =================
        const int mw = wid >> 2;          // m-warp 0..1 -> rows mw*32
        const int nw = wid & 3;           // n-warp 0..3 -> experts nw*16
        const uint32_t a_base = smbase + (uint32_t)((mw * 32) * RSTR)
                              + (uint32_t)((lane & 15) * RSTR + (lane >> 4) * 16);
        const uint32_t b_base = smbase + (uint32_t)((nw * 16) * RSTR)
                              + (uint32_t)(((lane & 7) + ((lane >> 4) & 1) * 8) * RSTR
                                           + ((lane >> 3) & 1) * 16);

        float c0[2][2][4], c1[2][2][4];
        #pragma unroll
        for (int i = 0; i < 2; i++)
            #pragma unroll
            for (int j = 0; j < 2; j++)
                #pragma unroll
                for (int k = 0; k < 4; k++) { c0[i][j][k] = 0.0f; c1[i][j][k] = 0.0f; }

        int stg = 0, ph = 0;
        for (int tile = 0; tile < KT; tile++) {
            const uint32_t full_s  = full_b  + stg * 8;
            const uint32_t empty_s = empty_b + stg * 8;
            const uint32_t so = (uint32_t)(stg * STAGE_B);

            MBAR_WAIT(full_s, ph);

            #pragma unroll
            for (int ks = 0; ks < 2; ks++) {
                const uint32_t ko = (uint32_t)(ks * 32);
                uint32_t ah[2][4], am[2][4], bh[2][2], bm[2][2];
                #pragma unroll
                for (int mt = 0; mt < 2; mt++) {
                    uint32_t ab = a_base + so + (uint32_t)(mt * 16 * RSTR) + ko;
                    ldsm4(ah[mt][0], ah[mt][1], ah[mt][2], ah[mt][3], ab + AH_OFF);
                    ldsm4(am[mt][0], am[mt][1], am[mt][2], am[mt][3], ab + AM_OFF);
                }
                {
                    uint32_t bb = b_base + so + ko;
                    uint32_t r0, r1, r2, r3;
                    ldsm4(r0, r1, r2, r3, bb + BH_OFF);
                    bh[0][0] = r0; bh[0][1] = r1; bh[1][0] = r2; bh[1][1] = r3;
                    ldsm4(r0, r1, r2, r3, bb + BM_OFF);
                    bm[0][0] = r0; bm[0][1] = r1; bm[1][0] = r2; bm[1][1] = r3;
                }
                #pragma unroll
                for (int mt = 0; mt < 2; mt++)
                    #pragma unroll
                    for (int nt = 0; nt < 2; nt++) {
                        mma16816(c0[mt][nt], ah[mt], bh[nt]);
                        mma16816(c1[mt][nt], ah[mt], bm[nt]);
                        mma16816(c1[mt][nt], am[mt], bh[nt]);
                    }
            }

            MBAR_ARRIVE(empty_s);   // fragments latched; stage reusable
            stg++; if (stg == NSTAGE) { stg = 0; ph ^= 1; }
        }

        // stash accumulators -> wait for whole CTA below, then write logits
        __syncthreads();   // (consumers side) -- paired with producers' barrier below
        float* Lsm = reinterpret_cast<float*>(dsm);
        #pragma unroll
        for (int mt = 0; mt < 2; mt++)
            #pragma unroll
            for (int nt = 0; nt < 2; nt++) {
                int r0 = mw * 32 + mt * 16 + (lane >> 2);
                int cc = nw * 16 + nt * 8 + (lane & 3) * 2;
                Lsm[r0 * LSTR + cc]           = c0[mt][nt][0] + c1[mt][nt][0] * INVS;
                Lsm[r0 * LSTR + cc + 1]       = c0[mt][nt][1] + c1[mt][nt][1] * INVS;
                Lsm[(r0 + 8) * LSTR + cc]     = c0[mt][nt][2] + c1[mt][nt][2] * INVS;
                Lsm[(r0 + 8) * LSTR + cc + 1] = c0[mt][nt][3] + c1[mt][nt][3] * INVS;
            }
    }

    if (wid >= 8) __syncthreads();   // producers join the consumers' barrier
    __syncthreads();                 // logits visible to everyone

    // ---- epilogue: threads 0..255, 4 per token, 16 experts each ----
    float ent = 0.0f, conf = 0.0f;
    if (t < 256) {
        float* Lsm = reinterpret_cast<float*>(dsm);
        const int q  = t & 3;
        const int tl = t >> 2;
        const int tok = mbase + tl;
        const float* L = &Lsm[tl * LSTR + q * 16];

        float m1 = -1e30f, m2 = -1e30f;
        int i1 = q * 16, i2 = q * 16;
        #pragma unroll
        for (int e = 0; e < 16; e++) {
            float v = L[e];
            int id = q * 16 + e;
            if (v > m1)      { m2 = m1; i2 = i1; m1 = v; i1 = id; }
            else if (v > m2) { m2 = v;  i2 = id; }
        }
        #pragma unroll
        for (int o = 1; o <= 2; o <<= 1) {
            float om1 = __shfl_xor_sync(0xffffffffu, m1, o);
            float om2 = __shfl_xor_sync(0xffffffffu, m2, o);
            int   oi1 = __shfl_xor_sync(0xffffffffu, i1, o);
            int   oi2 = __shfl_xor_sync(0xffffffffu, i2, o);
            if (ordgt(om1, oi1, m1, i1)) {
                if (ordgt(m1, i1, om2, oi2)) { m2 = m1; i2 = i1; }
                else                         { m2 = om2; i2 = oi2; }
                m1 = om1; i1 = oi1;
            } else {
                if (ordgt(om1, oi1, m2, i2)) { m2 = om1; i2 = oi1; }
            }
        }

        float ex[16];
        float Z = 0.0f;
        #pragma unroll
        for (int e = 0; e < 16; e++) {
            ex[e] = __expf(L[e] - m1);
            Z += ex[e];
        }
        Z += __shfl_xor_sync(0xffffffffu, Z, 1);
        Z += __shfl_xor_sync(0xffffffffu, Z, 2);
        const float invZ = 1.0f / Z;

        float4* dst = reinterpret_cast<float4*>(out + OFF_P + (size_t)tok * NEXP + q * 16);
        #pragma unroll
        for (int i = 0; i < 4; i++) {
            float p0 = ex[4*i+0] * invZ;
            float p1 = ex[4*i+1] * invZ;
            float p2 = ex[4*i+2] * invZ;
            float p3 = ex[4*i+3] * invZ;
            ent -= p0 * __logf(p0 + 1e-10f) + p1 * __logf(p1 + 1e-10f)
                 + p2 * __logf(p2 + 1e-10f) + p3 * __logf(p3 + 1e-10f);
            dst[i] = make_float4(p0, p1, p2, p3);
        }
        ent += __shfl_xor_sync(0xffffffffu, ent, 1);
        ent += __shfl_xor_sync(0xffffffffu, ent, 2);

        if (q == 0) {
            float ed = __expf(m2 - m1);
            float w0 = 1.0f / (1.0f + ed);
            float w1 = ed * w0;
            *reinterpret_cast<float2*>(out + OFF_W + (size_t)tok * 2) = make_float2(w0, w1);
            *reinterpret_cast<float2*>(out + OFF_I + (size_t)tok * 2) = make_float2((float)i1, (float)i2);
            conf = w0;
            atomicAdd(&hist[i1], 1);
            atomicAdd(&hist[i2], 1);
        } else {
            ent = 0.0f;
        }

        #pragma unroll
        for (int o = 16; o > 0; o >>= 1) {
            ent  += __shfl_down_sync(0xffffffffu, ent,  o);
            conf += __shfl_down_sync(0xffffffffu, conf, o);
        }
        if (lane == 0) { atomicAdd(&g_ent, ent); atomicAdd(&g_conf, conf); }
    }

    __syncthreads();
    if (t < NEXP) { int c = hist[t]; if (c) atomicAdd(&g_counts[t], c); }

    // ---- last-CTA finalize ----
    __syncthreads();
    if (t == 0) {
        __threadfence();
        s_last = (atomicAdd(&g_done, 1) == NCTAS - 1) ? 1 : 0;
    }
    __syncthreads();
    if (s_last) {
        __threadfence();
        if (t == 0) {
            out[OFF_ENT]  = atomicAdd(&g_ent,  0.0f) * (1.0f / 16384.0f);
            out[OFF_CONF] = atomicAdd(&g_conf, 0.0f) * (1.0f / 16384.0f);
        }
        if (t < NEXP)
            out[OFF_UTIL + t] = (float)atomicAdd(&g_counts[t], 0) * (1.0f / 32768.0f);
    }
}

extern "C" void kernel_launch(void* const* d_in, const int* in_sizes, int n_in,
                              void* d_out, int out_size) {
    const float* x = (const float*)d_in[0];   // [4,4096,2048] fp32
    const float* W = (const float*)d_in[1];   // [64,2048] fp32
    float* out = (float*)d_out;

    cudaFuncSetAttribute(router_kernel, cudaFuncAttributeMaxDynamicSharedMemorySize, DSM_BYTES);

    prep_kernel<<<128, 256>>>(W);
    router_kernel<<<NCTAS, NTHREADS, DSM_BYTES>>>(x, out);
}

// round 17
// speedup vs baseline: 1.5063x; 1.5063x over previous
#include <cuda_runtime.h>
#include <cuda_fp16.h>
#include <cstdint>

// ---------------- problem constants ----------------
#define T_TOKENS 16384
#define DMODEL   2048
#define NEXP     64
#define MT       64
#define NCTAS    (T_TOKENS / MT)      // 256
#define NTHREADS 256
#define BK       32
#define KT       (DMODEL / BK)        // 64
#define SCALE    2048.0f
#define INVS     (1.0f / 2048.0f)

// ---------------- output layout (fp32, reference return order) ----------------
#define OFF_W    ((size_t)0)
#define OFF_I    ((size_t)32768)
#define OFF_P    ((size_t)65536)
#define OFF_ENT  ((size_t)1114112)
#define OFF_CONF ((size_t)1114113)
#define OFF_UTIL ((size_t)1114114)

// ---------------- smem stage layout (5-stage ring) ----------------
// A: raw fp32, 64 rows x 128B data, 160B stride (row step = 40 banks = +8 mod 32:
//    16-lane LDS.64 phases cover all 32 banks exactly once -> conflict-free).
// B: fp16 limbs, 64 rows x 64B data, 80B stride (proven ldmatrix-conflict-free).
#define AROWB    160
#define A_BYTES  (64 * AROWB)                // 10240
#define BH_OFF   A_BYTES                     // 10240
#define BM_OFF   (A_BYTES + 64 * 80)         // 15360
#define STAGE_BYTES (A_BYTES + 2 * 64 * 80)  // 20480
#define NSTAGE   5
#define DEPTH    4                           // groups in flight
#define DSM_BYTES (NSTAGE * STAGE_BYTES)     // 102400
#define BSTR     80
#define LSTR     66                          // logits row stride (floats)

// ---------------- device globals ----------------
__device__ __half g_Wh[NEXP * DMODEL];
__device__ __half g_Wm[NEXP * DMODEL];
__device__ float  g_ent;
__device__ float  g_conf;
__device__ int    g_counts[NEXP];
__device__ int    g_done;

// ---------------- helpers ----------------
__device__ __forceinline__ uint32_t smem_u32(const void* p) {
    uint32_t a;
    asm("{ .reg .u64 t; cvta.to.shared.u64 t, %1; cvt.u32.u64 %0, t; }" : "=r"(a) : "l"(p));
    return a;
}
#define CP_ASYNC16(dst, src) \
    asm volatile("cp.async.cg.shared.global [%0], [%1], 16;" :: "r"(dst), "l"(src) : "memory")
#define CP_COMMIT() asm volatile("cp.async.commit_group;" ::: "memory")
#define CP_WAIT3()  asm volatile("cp.async.wait_group 3;" ::: "memory")
#define LDS64F(f, addr) \
    asm volatile("ld.shared.v2.f32 {%0,%1}, [%2];" : "=f"((f).x), "=f"((f).y) : "r"(addr))

__device__ __forceinline__ void ldsm4(uint32_t& r0, uint32_t& r1, uint32_t& r2, uint32_t& r3, uint32_t a) {
    asm volatile("ldmatrix.sync.aligned.m8n8.x4.shared.b16 {%0,%1,%2,%3}, [%4];"
                 : "=r"(r0), "=r"(r1), "=r"(r2), "=r"(r3) : "r"(a));
}
__device__ __forceinline__ void mma16816(float* c, const uint32_t* a, const uint32_t* b) {
    asm volatile("mma.sync.aligned.m16n8k16.row.col.f32.f16.f16.f32 "
                 "{%0,%1,%2,%3},{%4,%5,%6,%7},{%8,%9},{%0,%1,%2,%3};"
                 : "+f"(c[0]), "+f"(c[1]), "+f"(c[2]), "+f"(c[3])
                 : "r"(a[0]), "r"(a[1]), "r"(a[2]), "r"(a[3]), "r"(b[0]), "r"(b[1]));
}

// two-limb fp16 split of a float pair -> packed H and scaled-M half2s
__device__ __forceinline__ void cvt2(float a, float b, uint32_t& H, uint32_t& M) {
    __half2 h = __floats2half2_rn(a, b);
    float2 hf = __half22float2(h);
    __half2 m = __floats2half2_rn((a - hf.x) * SCALE, (b - hf.y) * SCALE);
    H = *reinterpret_cast<uint32_t*>(&h);
    M = *reinterpret_cast<uint32_t*>(&m);
}

// strict ordering with lowest-index tie-break (matches jax top_k)
__device__ __forceinline__ bool ordgt(float a, int ia, float b, int ib) {
    return (a > b) || (a == b && ia < ib);
}

// ---------------- prep: zero stats + split W into fp16 limbs ----------------
__global__ void prep_kernel(const float* __restrict__ W) {
    if (blockIdx.x == 0) {
        if (threadIdx.x == 0) { g_ent = 0.0f; g_conf = 0.0f; g_done = 0; }
        if (threadIdx.x < NEXP) g_counts[threadIdx.x] = 0;
    }
    int i = (blockIdx.x * 256 + threadIdx.x) * 4;
    if (i < NEXP * DMODEL) {
        float4 f = *(const float4*)(W + i);
        uint32_t h0, m0, h1, m1;
        cvt2(f.x, f.y, h0, m0);
        cvt2(f.z, f.w, h1, m1);
        *(uint2*)(g_Wh + i) = make_uint2(h0, h1);
        *(uint2*)(g_Wm + i) = make_uint2(m0, m1);
    }
}

// ---------------- main fused router ----------------
__global__ __launch_bounds__(NTHREADS, 2)
void router_kernel(const float* __restrict__ x, float* __restrict__ out) {
    extern __shared__ __align__(16) char dsm[];
    __shared__ int hist[NEXP];
    __shared__ int s_last;

    const int t    = threadIdx.x;
    const int wid  = t >> 5;
    const int lane = t & 31;
    const int mbase = blockIdx.x * MT;
    const uint32_t smbase = smem_u32(dsm);

    if (t < NEXP) hist[t] = 0;

    // cp.async maps: row = t>>2 (0..63), chunk = t&3
    const int cr = t >> 2;
    const int cq = t & 3;
    const uint32_t aDst  = smbase + (uint32_t)(cr * AROWB + cq * 32);    // 2 x 16B
    const uint32_t bDstH = smbase + BH_OFF + (uint32_t)(cr * BSTR + cq * 16);
    const uint32_t bDstM = smbase + BM_OFF + (uint32_t)(cr * BSTR + cq * 16);
    const float*  aSrc  = x + (size_t)(mbase + cr) * DMODEL + cq * 8;
    const __half* bSrcH = g_Wh + (size_t)cr * DMODEL + cq * 8;
    const __half* bSrcM = g_Wm + (size_t)cr * DMODEL + cq * 8;

    // warps: 4m x 2k; each M16 x N64, k16 (A rows owned by exactly one warp)
    const int ks = wid >> 2;          // k16 half of the 32-k tile
    const int wq = wid & 3;           // m-warp: rows wq*16 .. +15

    // A fragment LDS addresses (fp32): row = wq*16 + (lane>>2), col = (lane&3)*2 + ks*16
    const uint32_t aL0 = (uint32_t)((wq * 16 + (lane >> 2)) * AROWB + ((lane & 3) * 2 + ks * 16) * 4);

    // B ldmatrix per-lane byte offset
    const uint32_t b_l_off = (uint32_t)(((lane & 7) + ((lane >> 4) & 1) * 8) * BSTR
                                        + ((lane >> 3) & 1) * 16 + ks * 32);

    float c0[8][4], c1[8][4];
    #pragma unroll
    for (int j = 0; j < 8; j++)
        #pragma unroll
        for (int k = 0; k < 4; k++) { c0[j][k] = 0.0f; c1[j][k] = 0.0f; }

    // ---- prologue: issue stages 0..3 (DEPTH groups in flight) ----
    #pragma unroll
    for (int s = 0; s < DEPTH; s++) {
        const uint32_t st = (uint32_t)(s * STAGE_BYTES);
        const size_t so = (size_t)s * BK;
        CP_ASYNC16(aDst + st,      (const void*)(aSrc + so));
        CP_ASYNC16(aDst + st + 16, (const void*)(aSrc + so + 4));
        CP_ASYNC16(bDstH + st, (const void*)(bSrcH + so));
        CP_ASYNC16(bDstM + st, (const void*)(bSrcM + so));
        CP_COMMIT();
    }

    int stage = 0;
    for (int tile = 0; tile < KT; tile++) {
        CP_WAIT3();        // group(tile) complete (3 newer groups may be pending)
        __syncthreads();   // stage visible to all warps; compute(tile-1) closed

        // ---- issue tile+DEPTH into the stage freed by compute(tile-1) ----
        if (tile + DEPTH < KT) {
            int ns = stage + DEPTH; if (ns >= NSTAGE) ns -= NSTAGE;
            const uint32_t st = (uint32_t)(ns * STAGE_BYTES);
            const size_t so = (size_t)(tile + DEPTH) * BK;
            CP_ASYNC16(aDst + st,      (const void*)(aSrc + so));
            CP_ASYNC16(aDst + st + 16, (const void*)(aSrc + so + 4));
            CP_ASYNC16(bDstH + st, (const void*)(bSrcH + so));
            CP_ASYNC16(bDstM + st, (const void*)(bSrcM + so));
        }
        CP_COMMIT();       // uniform group counting (empty near tail)

        const uint32_t cur = smbase + (uint32_t)(stage * STAGE_BYTES);

        // ---- A fragment: 4 x LDS.64 fp32 -> in-register limb split (no duplication) ----
        uint32_t ah[4], am[4];
        {
            float2 f0, f1, f2, f3;
            const uint32_t a0 = cur + aL0;
            LDS64F(f0, a0);                    // (r,   c)
            LDS64F(f1, a0 + 8 * AROWB);        // (r+8, c)
            LDS64F(f2, a0 + 32);               // (r,   c+8)
            LDS64F(f3, a0 + 8 * AROWB + 32);   // (r+8, c+8)
            cvt2(f0.x, f0.y, ah[0], am[0]);
            cvt2(f1.x, f1.y, ah[1], am[1]);
            cvt2(f2.x, f2.y, ah[2], am[2]);
            cvt2(f3.x, f3.y, ah[3], am[3]);
        }

        // ---- B fragments via ldmatrix: 4 x 16-expert groups per limb ----
        uint32_t bh[8][2], bm[8][2];
        #pragma unroll
        for (int np = 0; np < 4; np++) {
            uint32_t nb = cur + (uint32_t)(np * 16 * BSTR) + b_l_off;
            uint32_t r0, r1, r2, r3;
            ldsm4(r0, r1, r2, r3, nb + BH_OFF);
            bh[np*2][0] = r0; bh[np*2][1] = r1; bh[np*2+1][0] = r2; bh[np*2+1][1] = r3;
            ldsm4(r0, r1, r2, r3, nb + BM_OFF);
            bm[np*2][0] = r0; bm[np*2][1] = r1; bm[np*2+1][0] = r2; bm[np*2+1][1] = r3;
        }

        // ---- 3 limb products, M16 x N64 ----
        #pragma unroll
        for (int nt = 0; nt < 8; nt++) {
            mma16816(c0[nt], ah, bh[nt]);
            mma16816(c1[nt], ah, bm[nt]);
            mma16816(c1[nt], am, bh[nt]);
        }

        stage++; if (stage >= NSTAGE) stage = 0;
    }

    // ---- merge k-halves into logits smem: ks0 warps write, ks1 warps add ----
    __syncthreads();   // all reads of final stage done before overlay
    float* Lsm = reinterpret_cast<float*>(dsm);
    if (ks == 0) {
        #pragma unroll
        for (int nt = 0; nt < 8; nt++) {
            int r0 = wq * 16 + (lane >> 2);
            int cc = nt * 8 + (lane & 3) * 2;
            Lsm[r0 * LSTR + cc]           = c0[nt][0] + c1[nt][0] * INVS;
            Lsm[r0 * LSTR + cc + 1]       = c0[nt][1] + c1[nt][1] * INVS;
            Lsm[(r0 + 8) * LSTR + cc]     = c0[nt][2] + c1[nt][2] * INVS;
            Lsm[(r0 + 8) * LSTR + cc + 1] = c0[nt][3] + c1[nt][3] * INVS;
        }
    }
    __syncthreads();
    if (ks == 1) {
        #pragma unroll
        for (int nt = 0; nt < 8; nt++) {
            int r0 = wq * 16 + (lane >> 2);
            int cc = nt * 8 + (lane & 3) * 2;
            Lsm[r0 * LSTR + cc]           += c0[nt][0] + c1[nt][0] * INVS;
            Lsm[r0 * LSTR + cc + 1]       += c0[nt][1] + c1[nt][1] * INVS;
            Lsm[(r0 + 8) * LSTR + cc]     += c0[nt][2] + c1[nt][2] * INVS;
            Lsm[(r0 + 8) * LSTR + cc + 1] += c0[nt][3] + c1[nt][3] * INVS;
        }
    }
    __syncthreads();

    // ---- epilogue: 4 threads per token, 16 experts each ----
    const int q  = t & 3;
    const int tl = t >> 2;           // token local 0..63
    const int tok = mbase + tl;
    const float* L = &Lsm[tl * LSTR + q * 16];

    float m1 = -1e30f, m2 = -1e30f;
    int i1 = q * 16, i2 = q * 16;
    #pragma unroll
    for (int e = 0; e < 16; e++) {
        float v = L[e];
        int id = q * 16 + e;
        if (v > m1)      { m2 = m1; i2 = i1; m1 = v; i1 = id; }
        else if (v > m2) { m2 = v;  i2 = id; }
    }

    #pragma unroll
    for (int o = 1; o <= 2; o <<= 1) {
        float om1 = __shfl_xor_sync(0xffffffffu, m1, o);
        float om2 = __shfl_xor_sync(0xffffffffu, m2, o);
        int   oi1 = __shfl_xor_sync(0xffffffffu, i1, o);
        int   oi2 = __shfl_xor_sync(0xffffffffu, i2, o);
        if (ordgt(om1, oi1, m1, i1)) {
            if (ordgt(m1, i1, om2, oi2)) { m2 = m1; i2 = i1; }
            else                         { m2 = om2; i2 = oi2; }
            m1 = om1; i1 = oi1;
        } else {
            if (ordgt(om1, oi1, m2, i2)) { m2 = om1; i2 = oi1; }
        }
    }

    float ex[16];
    float Z = 0.0f;
    #pragma unroll
    for (int e = 0; e < 16; e++) {
        ex[e] = __expf(L[e] - m1);
        Z += ex[e];
    }
    Z += __shfl_xor_sync(0xffffffffu, Z, 1);
    Z += __shfl_xor_sync(0xffffffffu, Z, 2);
    const float invZ = 1.0f / Z;

    float ent = 0.0f;
    float4* dst = reinterpret_cast<float4*>(out + OFF_P + (size_t)tok * NEXP + q * 16);
    #pragma unroll
    for (int i = 0; i < 4; i++) {
        float p0 = ex[4*i+0] * invZ;
        float p1 = ex[4*i+1] * invZ;
        float p2 = ex[4*i+2] * invZ;
        float p3 = ex[4*i+3] * invZ;
        ent -= p0 * __logf(p0 + 1e-10f) + p1 * __logf(p1 + 1e-10f)
             + p2 * __logf(p2 + 1e-10f) + p3 * __logf(p3 + 1e-10f);
        dst[i] = make_float4(p0, p1, p2, p3);
    }
    ent += __shfl_xor_sync(0xffffffffu, ent, 1);
    ent += __shfl_xor_sync(0xffffffffu, ent, 2);

    float conf = 0.0f;
    if (q == 0) {
        float ed = __expf(m2 - m1);
        float w0 = 1.0f / (1.0f + ed);
        float w1 = ed * w0;
        *reinterpret_cast<float2*>(out + OFF_W + (size_t)tok * 2) = make_float2(w0, w1);
        *reinterpret_cast<float2*>(out + OFF_I + (size_t)tok * 2) = make_float2((float)i1, (float)i2);
        conf = w0;
        atomicAdd(&hist[i1], 1);
        atomicAdd(&hist[i2], 1);
    } else {
        ent = 0.0f;
    }

    #pragma unroll
    for (int o = 16; o > 0; o >>= 1) {
        ent  += __shfl_down_sync(0xffffffffu, ent,  o);
        conf += __shfl_down_sync(0xffffffffu, conf, o);
    }
    if (lane == 0) { atomicAdd(&g_ent, ent); atomicAdd(&g_conf, conf); }

    __syncthreads();
    if (t < NEXP) { int c = hist[t]; if (c) atomicAdd(&g_counts[t], c); }

    // ---- last-CTA finalize ----
    __syncthreads();
    if (t == 0) {
        __threadfence();
        s_last = (atomicAdd(&g_done, 1) == NCTAS - 1) ? 1 : 0;
    }
    __syncthreads();
    if (s_last) {
        __threadfence();
        if (t == 0) {
            out[OFF_ENT]  = atomicAdd(&g_ent,  0.0f) * (1.0f / 16384.0f);
            out[OFF_CONF] = atomicAdd(&g_conf, 0.0f) * (1.0f / 16384.0f);
        }
        if (t < NEXP)
            out[OFF_UTIL + t] = (float)atomicAdd(&g_counts[t], 0) * (1.0f / 32768.0f);
    }
}

extern "C" void kernel_launch(void* const* d_in, const int* in_sizes, int n_in,
                              void* d_out, int out_size) {
    const float* x = (const float*)d_in[0];   // [4,4096,2048] fp32
    const float* W = (const float*)d_in[1];   // [64,2048] fp32
    float* out = (float*)d_out;

    cudaFuncSetAttribute(router_kernel, cudaFuncAttributeMaxDynamicSharedMemorySize, DSM_BYTES);

    prep_kernel<<<128, 256>>>(W);
    router_kernel<<<NCTAS, NTHREADS, DSM_BYTES>>>(x, out);
}